// round 16
// baseline (speedup 1.0000x reference)
#include <cuda_runtime.h>
#include <cuda_bf16.h>
#include <cstdint>

typedef unsigned long long u64;
typedef unsigned int u32;

// ---------------- problem constants ----------------
constexpr int D = 512, NCODES = 1024;
constexpr long long NBT = 32768;
constexpr long long Z_OFF = 0, LOSS_OFF = 16777216, DIST_OFF = 16777217, IDX_OFF = 50331649;

constexpr int BM = 128;      // rows per CTA
constexpr int BN = 128;      // codes per n-chunk
constexpr int BK = 64;       // bf16 k per chunk = 128B tile rows

constexpr int TILE = 16384;          // 128 rows x 128B, pre-swizzled bf16-hi
constexpr int STAGE = 2 * TILE;      // A tile + B tile = 32KB
constexpr int DSMEM = 3 * STAGE + 1024;
constexpr int KC_PER_NC = D / BK;                  // 8
constexpr int ITERS = (NCODES / BN) * KC_PER_NC;   // 64

constexpr float TAU = 0.05f;         // ambiguity threshold (>=5x worst bf16 dist err)

// ---------------- device scratch ----------------
__device__ __align__(128) unsigned char g_Rt[(NBT / BM) * KC_PER_NC * TILE];    // 32MB
__device__ __align__(128) unsigned char g_Et[(NCODES / BM) * KC_PER_NC * TILE]; // 1MB
__device__ float  g_z2[NBT];
__device__ float  g_e2[NCODES];
__device__ float2 g_bm[NBT];         // (min1, min2) cheap dist per row
__device__ int    g_bidx[NBT];       // idx of min1
__device__ double g_loss_acc;

// ---------------- PTX helpers (sm_90-baseline: safe for compute_103) -------
__device__ __forceinline__ u32 smem_u32(const void* p) {
    u32 a;
    asm("{ .reg .u64 t; cvta.to.shared.u64 t, %1; cvt.u32.u64 %0, t; }" : "=r"(a) : "l"(p));
    return a;
}
#define SW128(o) ((o) ^ (((o) >> 3) & 0x70))

#define MBAR_INIT(a, c) asm volatile("mbarrier.init.shared.b64 [%0], %1;" :: "r"(a), "r"(c) : "memory")
#define MBAR_ARRIVE(a)  asm volatile("mbarrier.arrive.shared.b64 _, [%0];" :: "r"(a) : "memory")
#define MBAR_EXPECT_TX(a, b) \
    asm volatile("mbarrier.arrive.expect_tx.shared.b64 _, [%0], %1;" :: "r"(a), "r"(b) : "memory")
#define MBAR_WAIT(a, ph) do {                                                          \
    u32 _a = (a), _p = (u32)(ph), _d;                                                  \
    asm volatile("{ .reg .pred p; mbarrier.try_wait.parity.acquire.cta.shared::cta.b64 p, [%1], %2; selp.b32 %0,1,0,p; }" \
                 : "=r"(_d) : "r"(_a), "r"(_p) : "memory");                            \
    if (!_d) {                                                                         \
        asm volatile("{ .reg .pred P1; WL%=: mbarrier.try_wait.parity.acquire.cta.shared::cta.b64 P1, [%0], %1, 0x989680;" \
                     " @P1 bra.uni WD%=; bra.uni WL%=; WD%=: }" :: "r"(_a), "r"(_p) : "memory"); \
    } } while (0)
#define BULK_G2S(dst, src, bytes, mbar)                                                \
    asm volatile("cp.async.bulk.shared::cluster.global.mbarrier::complete_tx::bytes "  \
                 "[%0], [%1], %2, [%3];"                                               \
                 :: "r"(dst), "l"(src), "r"(bytes), "r"(mbar) : "memory")
#define FENCE_ASYNC() asm volatile("fence.proxy.async.shared::cta;" ::: "memory")

__device__ __forceinline__ void ldsm4(u32* r, u32 addr) {
    asm volatile("ldmatrix.sync.aligned.m8n8.x4.shared.b16 {%0,%1,%2,%3}, [%4];"
                 : "=r"(r[0]), "=r"(r[1]), "=r"(r[2]), "=r"(r[3]) : "r"(addr));
}
__device__ __forceinline__ void mma16816(float* c, const u32* a, u32 b0, u32 b1) {
    asm volatile("mma.sync.aligned.m16n8k16.row.col.f32.bf16.bf16.f32 "
                 "{%0,%1,%2,%3}, {%4,%5,%6,%7}, {%8,%9}, {%0,%1,%2,%3};"
                 : "+f"(c[0]), "+f"(c[1]), "+f"(c[2]), "+f"(c[3])
                 : "r"(a[0]), "r"(a[1]), "r"(a[2]), "r"(a[3]), "r"(b0), "r"(b1));
}

// ---------------- prep (merged): fp32 -> bf16-hi tiles + exact row norms ----
__global__ void prep_all(const float* __restrict__ resid, const float* __restrict__ emb) {
    __shared__ float part[8];
    const bool is_r = blockIdx.x < 16384;
    const float* src = is_r ? resid : emb;
    unsigned char* dst = is_r ? g_Rt : g_Et;
    long long row = (long long)(is_r ? blockIdx.x : (blockIdx.x - 16384)) * 2 + (threadIdx.x >> 7);
    int t = threadIdx.x & 127;
    if (!is_r && blockIdx.x == 16384 && threadIdx.x == 0) g_loss_acc = 0.0;

    float4 v = *(const float4*)(src + row * D + t * 4);
    {
        __nv_bfloat162 h01{__float2bfloat16(v.x), __float2bfloat16(v.y)};
        __nv_bfloat162 h23{__float2bfloat16(v.z), __float2bfloat16(v.w)};
        const int blk = (int)(row >> 7), m = (int)(row & 127);
        const int kc = t >> 4, c0 = (t & 15) * 4;
        unsigned char* tile = dst + ((size_t)blk * KC_PER_NC + kc) * TILE;
        u32 off = SW128((u32)(m * 128 + c0 * 2));
        *(u64*)(tile + off) = (u64)(*(u32*)&h01) | ((u64)(*(u32*)&h23) << 32);
    }
    float s = v.x * v.x + v.y * v.y + v.z * v.z + v.w * v.w;
    #pragma unroll
    for (int k = 16; k; k >>= 1) s += __shfl_xor_sync(0xffffffffu, s, k);
    if ((threadIdx.x & 31) == 0) part[threadIdx.x >> 5] = s;
    __syncthreads();
    if (t == 0) {
        int b = (threadIdx.x >> 7) * 4;
        float n = part[b] + part[b + 1] + part[b + 2] + part[b + 3];
        if (is_r) g_z2[row] = n; else g_e2[row] = n;
    }
}

// ---------------- main: bulk-TMA-fed bf16 GEMM, dist + (min1,idx1,min2) -----
// mbarrier producer/consumer pipeline, dedicated producer = tid 0 (round-13).
__global__ void __launch_bounds__(256, 2) vq_main(float* __restrict__ out) {
    extern __shared__ char dsm[];
    __shared__ __align__(8) u64 s_full[3];
    __shared__ __align__(8) u64 s_empty[3];
    __shared__ float z2s[BM];
    __shared__ float e2sh[NCODES];
    __shared__ float sV1[BM][2];
    __shared__ int   sI1[BM][2];
    __shared__ float sV2[BM][2];

    const int tid = threadIdx.x, wid = tid >> 5, lane = tid & 31;
    const int warp_m = wid & 3, warp_n = wid >> 2;
    const long long row0 = (long long)blockIdx.x * BM;

    u32 dyn = smem_u32(dsm);
    const u32 sbase = (dyn + 1023) & ~1023u;

    if (tid == 0) {
        #pragma unroll
        for (int s = 0; s < 3; ++s) {
            MBAR_INIT(smem_u32(&s_full[s]), 1);
            MBAR_INIT(smem_u32(&s_empty[s]), 8);
        }
        FENCE_ASYNC();
    }
    if (tid < BM) z2s[tid] = g_z2[row0 + tid];
    for (int i = tid; i < NCODES; i += 256) e2sh[i] = g_e2[i];
    __syncthreads();

    const unsigned char* Abase = g_Rt + (size_t)blockIdx.x * KC_PER_NC * TILE;

    if (tid == 0) {
        #pragma unroll
        for (int p = 0; p < 2; ++p) {
            const int nc2 = p >> 3, kc2 = p & 7;
            u32 mb = smem_u32(&s_full[p]);
            u32 st = sbase + (u32)(p * STAGE);
            MBAR_EXPECT_TX(mb, (u32)STAGE);
            BULK_G2S(st,        Abase + (size_t)kc2 * TILE, (u32)TILE, mb);
            BULK_G2S(st + TILE, g_Et + ((size_t)nc2 * KC_PER_NC + kc2) * TILE, (u32)TILE, mb);
        }
    }

    float m1[4], m2[4]; int i1[4];
    #pragma unroll
    for (int s = 0; s < 4; ++s) { m1[s] = 3.4e38f; m2[s] = 3.4e38f; i1[s] = 0; }

    float acc[2][8][4];

    for (int it = 0; it < ITERS; ++it) {
        const int nc = it >> 3, kc = it & 7;
        if (kc == 0) {
            #pragma unroll
            for (int mt = 0; mt < 2; ++mt)
                #pragma unroll
                for (int nt = 0; nt < 8; ++nt)
                    #pragma unroll
                    for (int q = 0; q < 4; ++q) acc[mt][nt][q] = 0.f;
        }
        // producer: prefetch iter it+2 into stage (it+2)%3 once its previous
        // consumption has fully drained (8 warp-arrives on empty)
        if (tid == 0 && it + 2 < ITERS) {
            const int j = it + 2, nc2 = j >> 3, kc2 = j & 7;
            const int s = j % 3, u = j / 3;
            if (u >= 1) MBAR_WAIT(smem_u32(&s_empty[s]), (u - 1) & 1);
            u32 mb = smem_u32(&s_full[s]);
            u32 st = sbase + (u32)(s * STAGE);
            MBAR_EXPECT_TX(mb, (u32)STAGE);
            BULK_G2S(st,        Abase + (size_t)kc2 * TILE, (u32)TILE, mb);
            BULK_G2S(st + TILE, g_Et + ((size_t)nc2 * KC_PER_NC + kc2) * TILE, (u32)TILE, mb);
        }
        // consumer: wait current stage full
        MBAR_WAIT(smem_u32(&s_full[it % 3]), (it / 3) & 1);

        const u32 Ab = sbase + (u32)((it % 3) * STAGE);
        const u32 Bb = Ab + TILE;

        #pragma unroll
        for (int ks = 0; ks < 4; ++ks) {
            const u32 kb = (u32)((ks * 2 + (lane >> 4)) << 4);
            u32 a[2][4];
            #pragma unroll
            for (int mt = 0; mt < 2; ++mt) {
                u32 rowoff = (u32)((warp_m * 32 + mt * 16 + (lane & 15)) << 7);
                ldsm4(a[mt], Ab + SW128(rowoff + kb));
            }
            #pragma unroll
            for (int ng = 0; ng < 4; ++ng) {
                u32 b[4];
                u32 rowoff = (u32)((warp_n * 64 + ng * 16 + (lane & 15)) << 7);
                ldsm4(b, Bb + SW128(rowoff + kb));
                #pragma unroll
                for (int mt = 0; mt < 2; ++mt)
                    #pragma unroll
                    for (int sb = 0; sb < 2; ++sb)
                        mma16816(acc[mt][ng * 2 + sb], a[mt], b[sb], b[sb + 2]);
            }
        }
        // this warp is done with the stage: fragments are register-resident
        if (lane == 0) MBAR_ARRIVE(smem_u32(&s_empty[it % 3]));

        if (kc == 7) {
            const int qr = lane >> 2, qc = lane & 3;
            #pragma unroll
            for (int mt = 0; mt < 2; ++mt) {
                const int ra = warp_m * 32 + mt * 16 + qr;
                const int rb = ra + 8;
                const float z2a = z2s[ra], z2b = z2s[rb];
                #pragma unroll
                for (int nt = 0; nt < 8; ++nt) {
                    const int col = nc * BN + warp_n * 64 + nt * 8 + qc * 2;
                    const float e0 = e2sh[col], e1 = e2sh[col + 1];
                    float d00 = fmaf(-2.f, acc[mt][nt][0], z2a + e0);
                    float d01 = fmaf(-2.f, acc[mt][nt][1], z2a + e1);
                    float d10 = fmaf(-2.f, acc[mt][nt][2], z2b + e0);
                    float d11 = fmaf(-2.f, acc[mt][nt][3], z2b + e1);
                    const int sa = mt * 2, sbs = mt * 2 + 1;
                    if (d00 < m1[sa]) { m2[sa] = m1[sa]; m1[sa] = d00; i1[sa] = col; }
                    else if (d00 < m2[sa]) m2[sa] = d00;
                    if (d01 < m1[sa]) { m2[sa] = m1[sa]; m1[sa] = d01; i1[sa] = col + 1; }
                    else if (d01 < m2[sa]) m2[sa] = d01;
                    if (d10 < m1[sbs]) { m2[sbs] = m1[sbs]; m1[sbs] = d10; i1[sbs] = col; }
                    else if (d10 < m2[sbs]) m2[sbs] = d10;
                    if (d11 < m1[sbs]) { m2[sbs] = m1[sbs]; m1[sbs] = d11; i1[sbs] = col + 1; }
                    else if (d11 < m2[sbs]) m2[sbs] = d11;
                    long long oa = DIST_OFF + (row0 + ra) * 1024 + col;
                    long long ob = DIST_OFF + (row0 + rb) * 1024 + col;
                    out[oa] = d00; out[oa + 1] = d01;
                    out[ob] = d10; out[ob + 1] = d11;
                }
            }
        }
    }

    // ---- reduce (m1,i1,m2) across quad lanes, then across warp_n halves ----
    #pragma unroll
    for (int s = 0; s < 4; ++s) {
        #pragma unroll
        for (int o = 1; o <= 2; o <<= 1) {
            float om1 = __shfl_xor_sync(0xffffffffu, m1[s], o);
            float om2 = __shfl_xor_sync(0xffffffffu, m2[s], o);
            int   oi1 = __shfl_xor_sync(0xffffffffu, i1[s], o);
            if (om1 < m1[s] || (om1 == m1[s] && oi1 < i1[s])) {
                m2[s] = fminf(m1[s], om2);
                m1[s] = om1; i1[s] = oi1;
            } else {
                m2[s] = fminf(m2[s], om1);
            }
        }
    }
    if ((lane & 3) == 0) {
        const int qr = lane >> 2;
        #pragma unroll
        for (int mt = 0; mt < 2; ++mt) {
            int ra = warp_m * 32 + mt * 16 + qr;
            sV1[ra][warp_n] = m1[mt * 2];     sI1[ra][warp_n] = i1[mt * 2];     sV2[ra][warp_n] = m2[mt * 2];
            sV1[ra + 8][warp_n] = m1[mt * 2 + 1]; sI1[ra + 8][warp_n] = i1[mt * 2 + 1]; sV2[ra + 8][warp_n] = m2[mt * 2 + 1];
        }
    }
    __syncthreads();
    if (tid < BM) {
        float a1 = sV1[tid][0], a2 = sV2[tid][0]; int ai = sI1[tid][0];
        float b1 = sV1[tid][1], b2 = sV2[tid][1]; int bi = sI1[tid][1];
        float f1, f2; int fi;
        if (b1 < a1 || (b1 == a1 && bi < ai)) { f1 = b1; fi = bi; f2 = fminf(a1, b2); }
        else                                  { f1 = a1; fi = ai; f2 = fminf(b1, a2); }
        g_bm[row0 + tid] = make_float2(f1, f2);
        g_bidx[row0 + tid] = fi;
    }
}

// ---------------- refine: 2 rows per warp (interleaved gathers for MLP) -----
__global__ void __launch_bounds__(256) refine(const float* __restrict__ resid,
                                              const float* __restrict__ emb,
                                              float* __restrict__ out) {
    __shared__ float wls[8];
    __shared__ int   sIdx[16];
    __shared__ float2 sMM[16];
    const int wid = threadIdx.x >> 5, lane = threadIdx.x & 31;
    const long long rowbase = (long long)blockIdx.x * 16;

    if (threadIdx.x < 16) {
        sIdx[threadIdx.x] = g_bidx[rowbase + threadIdx.x];
        sMM[threadIdx.x]  = g_bm[rowbase + threadIdx.x];
    }
    __syncthreads();

    long long rows[2] = { rowbase + wid * 2, rowbase + wid * 2 + 1 };
    int fin[2];

    #pragma unroll
    for (int rr = 0; rr < 2; ++rr) {
        const int slot = wid * 2 + rr;
        fin[rr] = sIdx[slot];
        const float2 mm = sMM[slot];
        if (mm.y - mm.x < TAU) {
            const long long row = rows[rr];
            const float* drow = out + DIST_OFF + row * 1024;
            float vals[32];
            #pragma unroll
            for (int j = 0; j < 32; ++j) vals[j] = drow[j * 32 + lane];
            const float thr = mm.x + TAU;
            const float* rp = resid + row * D;
            const float zz = g_z2[row];
            float bestd = 3.4e38f; int besti = 1 << 30;
            #pragma unroll
            for (int j = 0; j < 32; ++j) {
                u32 bal = __ballot_sync(0xffffffffu, vals[j] < thr);
                while (bal) {
                    int src = __ffs(bal) - 1;
                    bal &= bal - 1;
                    int c = j * 32 + src;
                    const float* ep = emb + (long long)c * D;
                    float part = 0.f;
                    #pragma unroll
                    for (int q = 0; q < 4; ++q) {
                        int i4 = (q * 32 + lane) * 4;
                        float4 rv = *(const float4*)(rp + i4);
                        float4 ev = *(const float4*)(ep + i4);
                        part += rv.x * ev.x + rv.y * ev.y + rv.z * ev.z + rv.w * ev.w;
                    }
                    #pragma unroll
                    for (int o = 16; o; o >>= 1) part += __shfl_xor_sync(0xffffffffu, part, o);
                    float dex = fmaf(-2.f, part, zz + g_e2[c]);
                    if (dex < bestd || (dex == bestd && c < besti)) { bestd = dex; besti = c; }
                }
            }
            fin[rr] = besti;
        }
    }

    if (lane == 0) {
        out[IDX_OFF + rows[0]] = (float)fin[0];
        out[IDX_OFF + rows[1]] = (float)fin[1];
    }

    // z_st gather + loss for both rows, loads interleaved for MLP
    const float* ep0 = emb + (long long)fin[0] * D;
    const float* ep1 = emb + (long long)fin[1] * D;
    const float* rp0 = resid + rows[0] * D;
    const float* rp1 = resid + rows[1] * D;
    float4 qv[2][4], rv[2][4];
    #pragma unroll
    for (int q = 0; q < 4; ++q) {
        int i4 = (q * 32 + lane) * 4;
        qv[0][q] = *(const float4*)(ep0 + i4);
        qv[1][q] = *(const float4*)(ep1 + i4);
        rv[0][q] = *(const float4*)(rp0 + i4);
        rv[1][q] = *(const float4*)(rp1 + i4);
    }
    float lsum = 0.f;
    #pragma unroll
    for (int rr = 0; rr < 2; ++rr) {
        #pragma unroll
        for (int q = 0; q < 4; ++q) {
            int i4 = (q * 32 + lane) * 4;
            *(float4*)(out + Z_OFF + rows[rr] * D + i4) = qv[rr][q];
            float d0 = qv[rr][q].x - rv[rr][q].x, d1 = qv[rr][q].y - rv[rr][q].y;
            float d2 = qv[rr][q].z - rv[rr][q].z, d3 = qv[rr][q].w - rv[rr][q].w;
            lsum += d0 * d0 + d1 * d1 + d2 * d2 + d3 * d3;
        }
    }
    #pragma unroll
    for (int o = 16; o; o >>= 1) lsum += __shfl_xor_sync(0xffffffffu, lsum, o);
    if (lane == 0) wls[wid] = lsum;
    __syncthreads();
    if (threadIdx.x == 0) {
        float s = 0.f;
        #pragma unroll
        for (int w = 0; w < 8; ++w) s += wls[w];
        atomicAdd(&g_loss_acc, (double)s);
    }
}

__global__ void finalize_kernel(float* __restrict__ out) {
    out[LOSS_OFF] = (float)(1.25 * g_loss_acc / 16777216.0);
}

extern "C" void kernel_launch(void* const* d_in, const int* in_sizes, int n_in,
                              void* d_out, int out_size) {
    const float* resid = (const float*)d_in[0];
    const float* emb   = (const float*)d_in[1];
    if (n_in >= 2 && in_sizes[0] == 524288 && in_sizes[1] == 16777216) {
        const float* t = resid; resid = emb; emb = t;
    }
    float* out = (float*)d_out;

    static int smem_set = 0;
    if (!smem_set) {
        cudaFuncSetAttribute(vq_main, cudaFuncAttributeMaxDynamicSharedMemorySize, DSMEM);
        smem_set = 1;
    }

    prep_all<<<16896, 256>>>(resid, emb);
    vq_main<<<256, 256, DSMEM>>>(out);
    refine<<<2048, 256>>>(resid, emb, out);
    finalize_kernel<<<1, 1>>>(out);
}

// round 17
// speedup vs baseline: 1.0639x; 1.0639x over previous
#include <cuda_runtime.h>
#include <cuda_bf16.h>
#include <cstdint>

typedef unsigned long long u64;
typedef unsigned int u32;

// ---------------- problem constants ----------------
constexpr int D = 512, NCODES = 1024;
constexpr long long NBT = 32768;
constexpr long long Z_OFF = 0, LOSS_OFF = 16777216, DIST_OFF = 16777217, IDX_OFF = 50331649;

constexpr int BM = 128;      // rows per CTA
constexpr int BN = 128;      // codes per n-chunk
constexpr int BK = 64;       // bf16 k per chunk = 128B tile rows

constexpr int TILE = 16384;          // 128 rows x 128B, pre-swizzled bf16-hi
constexpr int STAGE = 2 * TILE;      // A tile + B tile = 32KB
constexpr int DSMEM = 3 * STAGE + 1024;
constexpr int KC_PER_NC = D / BK;                  // 8
constexpr int ITERS = (NCODES / BN) * KC_PER_NC;   // 64

constexpr float TAU = 0.05f;         // ambiguity threshold (>=5x worst bf16 dist err)

// ---------------- device scratch ----------------
__device__ __align__(128) unsigned char g_Rt[(NBT / BM) * KC_PER_NC * TILE];    // 32MB
__device__ __align__(128) unsigned char g_Et[(NCODES / BM) * KC_PER_NC * TILE]; // 1MB
__device__ float  g_z2[NBT];
__device__ float  g_e2[NCODES];
__device__ float2 g_bm[NBT];         // (min1, min2) cheap dist per row
__device__ int    g_bidx[NBT];       // idx of min1
__device__ double g_loss_acc;

// ---------------- PTX helpers (sm_90-baseline: safe for compute_103) -------
__device__ __forceinline__ u32 smem_u32(const void* p) {
    u32 a;
    asm("{ .reg .u64 t; cvta.to.shared.u64 t, %1; cvt.u32.u64 %0, t; }" : "=r"(a) : "l"(p));
    return a;
}
#define SW128(o) ((o) ^ (((o) >> 3) & 0x70))

#define MBAR_INIT(a, c) asm volatile("mbarrier.init.shared.b64 [%0], %1;" :: "r"(a), "r"(c) : "memory")
#define MBAR_ARRIVE(a)  asm volatile("mbarrier.arrive.shared.b64 _, [%0];" :: "r"(a) : "memory")
#define MBAR_EXPECT_TX(a, b) \
    asm volatile("mbarrier.arrive.expect_tx.shared.b64 _, [%0], %1;" :: "r"(a), "r"(b) : "memory")
#define MBAR_WAIT(a, ph) do {                                                          \
    u32 _a = (a), _p = (u32)(ph), _d;                                                  \
    asm volatile("{ .reg .pred p; mbarrier.try_wait.parity.acquire.cta.shared::cta.b64 p, [%1], %2; selp.b32 %0,1,0,p; }" \
                 : "=r"(_d) : "r"(_a), "r"(_p) : "memory");                            \
    if (!_d) {                                                                         \
        asm volatile("{ .reg .pred P1; WL%=: mbarrier.try_wait.parity.acquire.cta.shared::cta.b64 P1, [%0], %1, 0x989680;" \
                     " @P1 bra.uni WD%=; bra.uni WL%=; WD%=: }" :: "r"(_a), "r"(_p) : "memory"); \
    } } while (0)
#define BULK_G2S(dst, src, bytes, mbar)                                                \
    asm volatile("cp.async.bulk.shared::cluster.global.mbarrier::complete_tx::bytes "  \
                 "[%0], [%1], %2, [%3];"                                               \
                 :: "r"(dst), "l"(src), "r"(bytes), "r"(mbar) : "memory")
#define FENCE_ASYNC() asm volatile("fence.proxy.async.shared::cta;" ::: "memory")

__device__ __forceinline__ void ldsm4(u32* r, u32 addr) {
    asm volatile("ldmatrix.sync.aligned.m8n8.x4.shared.b16 {%0,%1,%2,%3}, [%4];"
                 : "=r"(r[0]), "=r"(r[1]), "=r"(r[2]), "=r"(r[3]) : "r"(addr));
}
__device__ __forceinline__ void mma16816(float* c, const u32* a, u32 b0, u32 b1) {
    asm volatile("mma.sync.aligned.m16n8k16.row.col.f32.bf16.bf16.f32 "
                 "{%0,%1,%2,%3}, {%4,%5,%6,%7}, {%8,%9}, {%0,%1,%2,%3};"
                 : "+f"(c[0]), "+f"(c[1]), "+f"(c[2]), "+f"(c[3])
                 : "r"(a[0]), "r"(a[1]), "r"(a[2]), "r"(a[3]), "r"(b0), "r"(b1));
}

// ---------------- prep (merged): fp32 -> bf16-hi tiles + exact row norms ----
__global__ void prep_all(const float* __restrict__ resid, const float* __restrict__ emb) {
    __shared__ float part[8];
    const bool is_r = blockIdx.x < 16384;
    const float* src = is_r ? resid : emb;
    unsigned char* dst = is_r ? g_Rt : g_Et;
    long long row = (long long)(is_r ? blockIdx.x : (blockIdx.x - 16384)) * 2 + (threadIdx.x >> 7);
    int t = threadIdx.x & 127;
    if (!is_r && blockIdx.x == 16384 && threadIdx.x == 0) g_loss_acc = 0.0;

    float4 v = *(const float4*)(src + row * D + t * 4);
    {
        __nv_bfloat162 h01{__float2bfloat16(v.x), __float2bfloat16(v.y)};
        __nv_bfloat162 h23{__float2bfloat16(v.z), __float2bfloat16(v.w)};
        const int blk = (int)(row >> 7), m = (int)(row & 127);
        const int kc = t >> 4, c0 = (t & 15) * 4;
        unsigned char* tile = dst + ((size_t)blk * KC_PER_NC + kc) * TILE;
        u32 off = SW128((u32)(m * 128 + c0 * 2));
        *(u64*)(tile + off) = (u64)(*(u32*)&h01) | ((u64)(*(u32*)&h23) << 32);
    }
    float s = v.x * v.x + v.y * v.y + v.z * v.z + v.w * v.w;
    #pragma unroll
    for (int k = 16; k; k >>= 1) s += __shfl_xor_sync(0xffffffffu, s, k);
    if ((threadIdx.x & 31) == 0) part[threadIdx.x >> 5] = s;
    __syncthreads();
    if (t == 0) {
        int b = (threadIdx.x >> 7) * 4;
        float n = part[b] + part[b + 1] + part[b + 2] + part[b + 3];
        if (is_r) g_z2[row] = n; else g_e2[row] = n;
    }
}

// ---------------- main: bulk-TMA-fed bf16 GEMM, dist + (min1,idx1,min2) -----
// mbarrier producer/consumer pipeline, dedicated producer = tid 0 (round-13).
__global__ void __launch_bounds__(256, 2) vq_main(float* __restrict__ out) {
    extern __shared__ char dsm[];
    __shared__ __align__(8) u64 s_full[3];
    __shared__ __align__(8) u64 s_empty[3];
    __shared__ float z2s[BM];
    __shared__ float e2sh[NCODES];
    __shared__ float sV1[BM][2];
    __shared__ int   sI1[BM][2];
    __shared__ float sV2[BM][2];

    const int tid = threadIdx.x, wid = tid >> 5, lane = tid & 31;
    const int warp_m = wid & 3, warp_n = wid >> 2;
    const long long row0 = (long long)blockIdx.x * BM;

    u32 dyn = smem_u32(dsm);
    const u32 sbase = (dyn + 1023) & ~1023u;

    if (tid == 0) {
        #pragma unroll
        for (int s = 0; s < 3; ++s) {
            MBAR_INIT(smem_u32(&s_full[s]), 1);
            MBAR_INIT(smem_u32(&s_empty[s]), 8);
        }
        FENCE_ASYNC();
    }
    if (tid < BM) z2s[tid] = g_z2[row0 + tid];
    for (int i = tid; i < NCODES; i += 256) e2sh[i] = g_e2[i];
    __syncthreads();

    const unsigned char* Abase = g_Rt + (size_t)blockIdx.x * KC_PER_NC * TILE;

    if (tid == 0) {
        #pragma unroll
        for (int p = 0; p < 2; ++p) {
            const int nc2 = p >> 3, kc2 = p & 7;
            u32 mb = smem_u32(&s_full[p]);
            u32 st = sbase + (u32)(p * STAGE);
            MBAR_EXPECT_TX(mb, (u32)STAGE);
            BULK_G2S(st,        Abase + (size_t)kc2 * TILE, (u32)TILE, mb);
            BULK_G2S(st + TILE, g_Et + ((size_t)nc2 * KC_PER_NC + kc2) * TILE, (u32)TILE, mb);
        }
    }

    float m1[4], m2[4]; int i1[4];
    #pragma unroll
    for (int s = 0; s < 4; ++s) { m1[s] = 3.4e38f; m2[s] = 3.4e38f; i1[s] = 0; }

    float acc[2][8][4];

    for (int it = 0; it < ITERS; ++it) {
        const int nc = it >> 3, kc = it & 7;
        if (kc == 0) {
            #pragma unroll
            for (int mt = 0; mt < 2; ++mt)
                #pragma unroll
                for (int nt = 0; nt < 8; ++nt)
                    #pragma unroll
                    for (int q = 0; q < 4; ++q) acc[mt][nt][q] = 0.f;
        }
        // producer: prefetch iter it+2 into stage (it+2)%3 once drained
        if (tid == 0 && it + 2 < ITERS) {
            const int j = it + 2, nc2 = j >> 3, kc2 = j & 7;
            const int s = j % 3, u = j / 3;
            if (u >= 1) MBAR_WAIT(smem_u32(&s_empty[s]), (u - 1) & 1);
            u32 mb = smem_u32(&s_full[s]);
            u32 st = sbase + (u32)(s * STAGE);
            MBAR_EXPECT_TX(mb, (u32)STAGE);
            BULK_G2S(st,        Abase + (size_t)kc2 * TILE, (u32)TILE, mb);
            BULK_G2S(st + TILE, g_Et + ((size_t)nc2 * KC_PER_NC + kc2) * TILE, (u32)TILE, mb);
        }
        // consumer: wait current stage full
        MBAR_WAIT(smem_u32(&s_full[it % 3]), (it / 3) & 1);

        const u32 Ab = sbase + (u32)((it % 3) * STAGE);
        const u32 Bb = Ab + TILE;

        #pragma unroll
        for (int ks = 0; ks < 4; ++ks) {
            const u32 kb = (u32)((ks * 2 + (lane >> 4)) << 4);
            u32 a[2][4];
            #pragma unroll
            for (int mt = 0; mt < 2; ++mt) {
                u32 rowoff = (u32)((warp_m * 32 + mt * 16 + (lane & 15)) << 7);
                ldsm4(a[mt], Ab + SW128(rowoff + kb));
            }
            #pragma unroll
            for (int ng = 0; ng < 4; ++ng) {
                u32 b[4];
                u32 rowoff = (u32)((warp_n * 64 + ng * 16 + (lane & 15)) << 7);
                ldsm4(b, Bb + SW128(rowoff + kb));
                #pragma unroll
                for (int mt = 0; mt < 2; ++mt)
                    #pragma unroll
                    for (int sb = 0; sb < 2; ++sb)
                        mma16816(acc[mt][ng * 2 + sb], a[mt], b[sb], b[sb + 2]);
            }
        }
        // warp done with the stage (fragments register-resident; in-order issue)
        if (lane == 0) MBAR_ARRIVE(smem_u32(&s_empty[it % 3]));

        if (kc == 7) {
            const int qr = lane >> 2, qc = lane & 3;
            #pragma unroll
            for (int mt = 0; mt < 2; ++mt) {
                const int ra = warp_m * 32 + mt * 16 + qr;
                const int rb = ra + 8;
                const float z2a = z2s[ra], z2b = z2s[rb];
                #pragma unroll
                for (int nt = 0; nt < 8; ++nt) {
                    const int col = nc * BN + warp_n * 64 + nt * 8 + qc * 2;
                    const float e0 = e2sh[col], e1 = e2sh[col + 1];
                    float d00 = fmaf(-2.f, acc[mt][nt][0], z2a + e0);
                    float d01 = fmaf(-2.f, acc[mt][nt][1], z2a + e1);
                    float d10 = fmaf(-2.f, acc[mt][nt][2], z2b + e0);
                    float d11 = fmaf(-2.f, acc[mt][nt][3], z2b + e1);
                    const int sa = mt * 2, sbs = mt * 2 + 1;
                    if (d00 < m1[sa]) { m2[sa] = m1[sa]; m1[sa] = d00; i1[sa] = col; }
                    else if (d00 < m2[sa]) m2[sa] = d00;
                    if (d01 < m1[sa]) { m2[sa] = m1[sa]; m1[sa] = d01; i1[sa] = col + 1; }
                    else if (d01 < m2[sa]) m2[sa] = d01;
                    if (d10 < m1[sbs]) { m2[sbs] = m1[sbs]; m1[sbs] = d10; i1[sbs] = col; }
                    else if (d10 < m2[sbs]) m2[sbs] = d10;
                    if (d11 < m1[sbs]) { m2[sbs] = m1[sbs]; m1[sbs] = d11; i1[sbs] = col + 1; }
                    else if (d11 < m2[sbs]) m2[sbs] = d11;
                    long long oa = DIST_OFF + (row0 + ra) * 1024 + col;
                    long long ob = DIST_OFF + (row0 + rb) * 1024 + col;
                    out[oa] = d00; out[oa + 1] = d01;
                    out[ob] = d10; out[ob + 1] = d11;
                }
            }
        }
    }

    // ---- reduce (m1,i1,m2) across quad lanes, then across warp_n halves ----
    #pragma unroll
    for (int s = 0; s < 4; ++s) {
        #pragma unroll
        for (int o = 1; o <= 2; o <<= 1) {
            float om1 = __shfl_xor_sync(0xffffffffu, m1[s], o);
            float om2 = __shfl_xor_sync(0xffffffffu, m2[s], o);
            int   oi1 = __shfl_xor_sync(0xffffffffu, i1[s], o);
            if (om1 < m1[s] || (om1 == m1[s] && oi1 < i1[s])) {
                m2[s] = fminf(m1[s], om2);
                m1[s] = om1; i1[s] = oi1;
            } else {
                m2[s] = fminf(m2[s], om1);
            }
        }
    }
    if ((lane & 3) == 0) {
        const int qr = lane >> 2;
        #pragma unroll
        for (int mt = 0; mt < 2; ++mt) {
            int ra = warp_m * 32 + mt * 16 + qr;
            sV1[ra][warp_n] = m1[mt * 2];     sI1[ra][warp_n] = i1[mt * 2];     sV2[ra][warp_n] = m2[mt * 2];
            sV1[ra + 8][warp_n] = m1[mt * 2 + 1]; sI1[ra + 8][warp_n] = i1[mt * 2 + 1]; sV2[ra + 8][warp_n] = m2[mt * 2 + 1];
        }
    }
    __syncthreads();
    if (tid < BM) {
        float a1 = sV1[tid][0], a2 = sV2[tid][0]; int ai = sI1[tid][0];
        float b1 = sV1[tid][1], b2 = sV2[tid][1]; int bi = sI1[tid][1];
        float f1, f2; int fi;
        if (b1 < a1 || (b1 == a1 && bi < ai)) { f1 = b1; fi = bi; f2 = fminf(a1, b2); }
        else                                  { f1 = a1; fi = ai; f2 = fminf(b1, a2); }
        g_bm[row0 + tid] = make_float2(f1, f2);
        g_bidx[row0 + tid] = fi;
    }
}

// ---------------- refine: idx + z_st gather + loss (NO resid read fast path)
// loss per row = dist(row, idx): cheap m1 for unambiguous rows (error ~1e-3,
// averaged over 32768 rows -> ~1e-8 on loss), exact bestd for ambiguous ones.
__global__ void __launch_bounds__(256) refine(const float* __restrict__ resid,
                                              const float* __restrict__ emb,
                                              float* __restrict__ out) {
    __shared__ float wls[8];
    __shared__ int   sIdx[8];
    __shared__ float2 sMM[8];
    const int wid = threadIdx.x >> 5, lane = threadIdx.x & 31;
    const long long rowbase = (long long)blockIdx.x * 8;
    const long long row = rowbase + wid;

    if (threadIdx.x < 8) {
        sIdx[threadIdx.x] = g_bidx[rowbase + threadIdx.x];
        sMM[threadIdx.x]  = g_bm[rowbase + threadIdx.x];
    }
    __syncthreads();

    int finali = sIdx[wid];
    const float2 mm = sMM[wid];
    float loss_part = mm.x;      // cheap dist of chosen code (fast path)

    if (mm.y - mm.x < TAU) {
        // ambiguous: batch-load cheap dist row, exact fp32 recompute candidates
        const float* drow = out + DIST_OFF + row * 1024;
        float vals[32];
        #pragma unroll
        for (int j = 0; j < 32; ++j) vals[j] = drow[j * 32 + lane];
        const float thr = mm.x + TAU;
        const float* rp = resid + row * D;
        const float zz = g_z2[row];
        float bestd = 3.4e38f; int besti = 1 << 30;
        #pragma unroll
        for (int j = 0; j < 32; ++j) {
            u32 bal = __ballot_sync(0xffffffffu, vals[j] < thr);
            while (bal) {
                int src = __ffs(bal) - 1;
                bal &= bal - 1;
                int c = j * 32 + src;
                const float* ep = emb + (long long)c * D;
                float part = 0.f;
                #pragma unroll
                for (int q = 0; q < 4; ++q) {
                    int i4 = (q * 32 + lane) * 4;
                    float4 rv = *(const float4*)(rp + i4);
                    float4 ev = *(const float4*)(ep + i4);
                    part += rv.x * ev.x + rv.y * ev.y + rv.z * ev.z + rv.w * ev.w;
                }
                #pragma unroll
                for (int o = 16; o; o >>= 1) part += __shfl_xor_sync(0xffffffffu, part, o);
                float dex = fmaf(-2.f, part, zz + g_e2[c]);
                if (dex < bestd || (dex == bestd && c < besti)) { bestd = dex; besti = c; }
            }
        }
        finali = besti;
        loss_part = bestd;       // exact dist of chosen code
    }

    if (lane == 0) out[IDX_OFF + row] = (float)finali;

    // z_st = emb[finali] — pure gather, no resid read
    const float* ep = emb + (long long)finali * D;
    float4 qv[4];
    #pragma unroll
    for (int q = 0; q < 4; ++q) {
        int i4 = (q * 32 + lane) * 4;
        qv[q] = *(const float4*)(ep + i4);
    }
    #pragma unroll
    for (int q = 0; q < 4; ++q) {
        int i4 = (q * 32 + lane) * 4;
        *(float4*)(out + Z_OFF + row * D + i4) = qv[q];
    }

    if (lane == 0) wls[wid] = loss_part;
    __syncthreads();
    if (threadIdx.x == 0) {
        float s = 0.f;
        #pragma unroll
        for (int w = 0; w < 8; ++w) s += wls[w];
        atomicAdd(&g_loss_acc, (double)s);
    }
}

__global__ void finalize_kernel(float* __restrict__ out) {
    out[LOSS_OFF] = (float)(1.25 * g_loss_acc / 16777216.0);
}

extern "C" void kernel_launch(void* const* d_in, const int* in_sizes, int n_in,
                              void* d_out, int out_size) {
    const float* resid = (const float*)d_in[0];
    const float* emb   = (const float*)d_in[1];
    if (n_in >= 2 && in_sizes[0] == 524288 && in_sizes[1] == 16777216) {
        const float* t = resid; resid = emb; emb = t;
    }
    float* out = (float*)d_out;

    static int smem_set = 0;
    if (!smem_set) {
        cudaFuncSetAttribute(vq_main, cudaFuncAttributeMaxDynamicSharedMemorySize, DSMEM);
        smem_set = 1;
    }

    prep_all<<<16896, 256>>>(resid, emb);
    vq_main<<<256, 256, DSMEM>>>(out);
    refine<<<4096, 256>>>(resid, emb, out);
    finalize_kernel<<<1, 1>>>(out);
}